// round 1
// baseline (speedup 1.0000x reference)
#include <cuda_runtime.h>

// CapsuleLayer dynamic routing, GB300 sm_103a.
// B=32, IN_CAPS=1152, P=64, NUM_CAPS=32, Q=64, NUM_ROUTING=3.
//
// Algebra used:
//   hat[b,i,c,q] = sum_p x[b,i,p] * W[i,c,p,q]
//   r0: c0[i,c]=softmax_c(bias[i,c]) (batch-independent) -> S0 accumulated in GEMM
//   v0 = squash(S0)
//   r1: b1 = bias + <hat, v0>_q ; S1 = sum_i softmax_c(b1) * hat ; v1 = squash(S1)
//   r2: b2 = bias + <hat, v0+v1>_q ; S2 = sum_i softmax_c(b2) * hat ; out = squash(S2)
// (b-updates are linear in hat, so b1 never needs to be materialized.)

#define BB 32
#define IC 1152
#define PP 64
#define NC 32
#define QQ 64
#define HAT_ELEMS (BB * IC * NC * QQ)  // 75,497,472 floats = 302 MB
#define SV (BB * NC * QQ)              // 65536

// ---------------- device scratch (static, allocation-free) ----------------
__device__ __align__(16) float g_hat[HAT_ELEMS];
__device__ __align__(16) float g_S0[SV];
__device__ __align__(16) float g_S1[SV];
__device__ __align__(16) float g_S2[SV];
__device__ __align__(16) float g_v0[SV];
__device__ __align__(16) float g_v01[SV];
__device__ __align__(16) float g_c0[IC * NC];

// ---------------- packed f32x2 helpers (Blackwell) ----------------
__device__ __forceinline__ unsigned long long pack2(float x, float y) {
    unsigned long long r;
    asm("mov.b64 %0, {%1, %2};" : "=l"(r)
        : "r"(__float_as_uint(x)), "r"(__float_as_uint(y)));
    return r;
}
__device__ __forceinline__ float2 unpack2(unsigned long long v) {
    unsigned int lo, hi;
    asm("mov.b64 {%0, %1}, %2;" : "=r"(lo), "=r"(hi) : "l"(v));
    return make_float2(__uint_as_float(lo), __uint_as_float(hi));
}
#define FMA2(d, a_, b_, c_) \
    asm("fma.rn.f32x2 %0, %1, %2, %3;" : "=l"(d) : "l"(a_), "l"(b_), "l"(c_))

union U64x2 { unsigned long long u[2]; float4 f; };

// ---------------- prep kernels ----------------
__global__ void zero_kernel() {
    int idx = blockIdx.x * blockDim.x + threadIdx.x;
    if (idx < SV) {
        g_S0[idx] = 0.f;
        g_S1[idx] = 0.f;
        g_S2[idx] = 0.f;
    }
}

// c0[i,c] = softmax over c of bias[i,c]; one warp per i
__global__ void bias_softmax_kernel(const float* __restrict__ bias) {
    int i = blockIdx.x;
    int lane = threadIdx.x;
    float bv = bias[i * NC + lane];
    float m = bv;
#pragma unroll
    for (int o = 16; o > 0; o >>= 1)
        m = fmaxf(m, __shfl_xor_sync(0xffffffffu, m, o));
    float e = __expf(bv - m);
    float se = e;
#pragma unroll
    for (int o = 16; o > 0; o >>= 1)
        se += __shfl_xor_sync(0xffffffffu, se, o);
    g_c0[i * NC + lane] = e / se;
}

// ---------------- GEMM: hat + S0 accumulation ----------------
// Grid: (NC/CGRP=16, IC/ICH=36), 64 threads.
// Thread tile: 8 b x 8 q (as 4 f32x2 q-pairs), K=64 loop, 32 i per CTA.
#define CGRP 2
#define ICH 32
#define WSROW 132  // 128 + 4 pad, keeps 16B alignment (132*4 = 528 = 16*33)

__global__ __launch_bounds__(64) void gemm_kernel(const float* __restrict__ x,
                                                  const float* __restrict__ W) {
    __shared__ __align__(16) float xs[BB * PP];      // [b][p]  8 KB
    __shared__ __align__(16) float ws[PP * WSROW];   // [p][cl*64+q] 33.8 KB

    int tid = threadIdx.x;
    int tn = tid & 15;      // 0..15 -> n dimension
    int tm = tid >> 4;      // 0..3  -> b groups of 8
    int cpair = blockIdx.x; // 0..15
    int i0 = blockIdx.y * ICH;
    int cl = tn >> 3;               // 0..1 (c within pair)
    int q0 = (tn & 7) << 3;         // 0..56
    int cg = cpair * CGRP + cl;     // global output capsule
    int n0 = cl * QQ + q0;

    unsigned long long s0acc[8][4];
#pragma unroll
    for (int k = 0; k < 8; k++)
#pragma unroll
        for (int j = 0; j < 4; j++) s0acc[k][j] = 0ULL;

    for (int ii = 0; ii < ICH; ii++) {
        int i = i0 + ii;
        // load x tile [32 x 64]: thread -> half row of one b
        {
            int bld = tid >> 1, half = tid & 1;
            const float4* src =
                (const float4*)(x + ((size_t)bld * IC + i) * PP + half * 32);
            float4* dst = (float4*)(xs + bld * PP + half * 32);
#pragma unroll
            for (int k = 0; k < 8; k++) dst[k] = src[k];
        }
        // load W block for (i, 2 capsules): 8192 contiguous floats, transpose c/p -> [p][cl*64+q]
        {
            const float4* src =
                (const float4*)(W + ((size_t)i * NC + cpair * CGRP) * PP * QQ);
            int j4 = tid;
#pragma unroll
            for (int k = 0; k < 32; k++, j4 += 64) {
                float4 v = src[j4];
                int clw = j4 >> 10;         // /1024 float4s per capsule
                int p = (j4 >> 4) & 63;     // 16 float4 per p-row
                int q4 = j4 & 15;
                *(float4*)(ws + p * WSROW + clw * QQ + q4 * 4) = v;
            }
        }
        __syncthreads();

        unsigned long long acc[8][4];
#pragma unroll
        for (int k = 0; k < 8; k++)
#pragma unroll
            for (int j = 0; j < 4; j++) acc[k][j] = 0ULL;

#pragma unroll 4
        for (int p = 0; p < PP; p++) {
            ulonglong2 w01 = *(const ulonglong2*)(ws + p * WSROW + n0);
            ulonglong2 w23 = *(const ulonglong2*)(ws + p * WSROW + n0 + 4);
#pragma unroll
            for (int k = 0; k < 8; k++) {
                float av = xs[(tm * 8 + k) * PP + p];
                unsigned long long a2 = pack2(av, av);
                FMA2(acc[k][0], a2, w01.x, acc[k][0]);
                FMA2(acc[k][1], a2, w01.y, acc[k][1]);
                FMA2(acc[k][2], a2, w23.x, acc[k][2]);
                FMA2(acc[k][3], a2, w23.y, acc[k][3]);
            }
        }

        // write hat tile + accumulate c0-weighted S0 partial
        float wgt = g_c0[i * NC + cg];
        unsigned long long w2 = pack2(wgt, wgt);
#pragma unroll
        for (int k = 0; k < 8; k++) {
            int b = tm * 8 + k;
            float* hp = g_hat + (((size_t)b * IC + i) * NC + cg) * QQ + q0;
            U64x2 u;
            u.u[0] = acc[k][0];
            u.u[1] = acc[k][1];
            *(float4*)hp = u.f;
            u.u[0] = acc[k][2];
            u.u[1] = acc[k][3];
            *(float4*)(hp + 4) = u.f;
#pragma unroll
            for (int j = 0; j < 4; j++)
                FMA2(s0acc[k][j], w2, acc[k][j], s0acc[k][j]);
        }
        __syncthreads();
    }

    // per-CTA partial -> global S0 (36 atomics per address total)
#pragma unroll
    for (int k = 0; k < 8; k++) {
        int b = tm * 8 + k;
        float* sp = g_S0 + ((size_t)b * NC + cg) * QQ + q0;
#pragma unroll
        for (int j = 0; j < 4; j++) {
            float2 f = unpack2(s0acc[k][j]);
            atomicAdd(sp + j * 2, f.x);
            atomicAdd(sp + j * 2 + 1, f.y);
        }
    }
}

// ---------------- routing pass (rounds 1 and 2) ----------------
// Grid: (IC/RICH=32, B=32), 256 threads. Reads hat once, accumulates S.
#define RICH 36

__global__ __launch_bounds__(256) void route_kernel(int round,
                                                    const float* __restrict__ bias) {
    __shared__ __align__(16) float vsh[NC * QQ];
    __shared__ __align__(16) float hs[NC * QQ];
    __shared__ __align__(16) float sacc[NC * QQ];
    __shared__ float tb[NC];
    __shared__ float csh[NC];

    const float* vin = (round == 1) ? g_v0 : g_v01;
    float* Sout = (round == 1) ? g_S1 : g_S2;

    int tid = threadIdx.x;
    int b = blockIdx.y;
    int i0 = blockIdx.x * RICH;
    int warp = tid >> 5, lane = tid & 31;

#pragma unroll
    for (int k = 0; k < 8; k++) {
        int idx = tid + 256 * k;
        vsh[idx] = vin[b * (NC * QQ) + idx];
        sacc[idx] = 0.f;
    }
    __syncthreads();

    for (int ii = 0; ii < RICH; ii++) {
        int i = i0 + ii;
        const float4* hp =
            (const float4*)(g_hat + (((size_t)b * IC + i) * NC) * QQ);
#pragma unroll
        for (int k = 0; k < 2; k++)
            ((float4*)hs)[tid + 256 * k] = hp[tid + 256 * k];
        __syncthreads();

        // logits: t[c] = bias[i,c] + <hat[b,i,c,:], v[b,c,:]>
#pragma unroll
        for (int cc = 0; cc < 4; cc++) {
            int c = warp * 4 + cc;
            float s = hs[c * QQ + lane] * vsh[c * QQ + lane] +
                      hs[c * QQ + 32 + lane] * vsh[c * QQ + 32 + lane];
#pragma unroll
            for (int o = 16; o > 0; o >>= 1)
                s += __shfl_down_sync(0xffffffffu, s, o);
            if (lane == 0) tb[c] = bias[i * NC + c] + s;
        }
        __syncthreads();

        if (warp == 0) {
            float bv = tb[lane];
            float m = bv;
#pragma unroll
            for (int o = 16; o > 0; o >>= 1)
                m = fmaxf(m, __shfl_xor_sync(0xffffffffu, m, o));
            float e = __expf(bv - m);
            float se = e;
#pragma unroll
            for (int o = 16; o > 0; o >>= 1)
                se += __shfl_xor_sync(0xffffffffu, se, o);
            csh[lane] = e / se;
        }
        __syncthreads();

#pragma unroll
        for (int k = 0; k < 8; k++) {
            int idx = tid + 256 * k;
            sacc[idx] += csh[idx >> 6] * hs[idx];
        }
        __syncthreads();
    }

#pragma unroll
    for (int k = 0; k < 8; k++) {
        int idx = tid + 256 * k;
        atomicAdd(&Sout[b * (NC * QQ) + idx], sacc[idx]);
    }
}

// ---------------- squash ----------------
// mode 0: v0 = squash(S0); mode 1: v01 = v0 + squash(S1); mode 2: out = squash(S2)
__global__ void squash_kernel(int mode, float* __restrict__ dout) {
    const float* S = (mode == 0) ? g_S0 : (mode == 1) ? g_S1 : g_S2;
    int vec = blockIdx.x;  // b*NC + c
    int lane = threadIdx.x;
    float x0 = S[vec * QQ + lane];
    float x1 = S[vec * QQ + 32 + lane];
    float ss = x0 * x0 + x1 * x1;
#pragma unroll
    for (int o = 16; o > 0; o >>= 1)
        ss += __shfl_xor_sync(0xffffffffu, ss, o);
    float sc = (ss > 0.f) ? (ss / (1.f + ss)) * rsqrtf(ss) : 0.f;
    float o0 = sc * x0, o1 = sc * x1;
    if (mode == 0) {
        g_v0[vec * QQ + lane] = o0;
        g_v0[vec * QQ + 32 + lane] = o1;
    } else if (mode == 1) {
        g_v01[vec * QQ + lane] = g_v0[vec * QQ + lane] + o0;
        g_v01[vec * QQ + 32 + lane] = g_v0[vec * QQ + 32 + lane] + o1;
    } else {
        dout[vec * QQ + lane] = o0;
        dout[vec * QQ + 32 + lane] = o1;
    }
}

// ---------------- launch ----------------
extern "C" void kernel_launch(void* const* d_in, const int* in_sizes, int n_in,
                              void* d_out, int out_size) {
    const float* x = (const float*)d_in[0];     // [32,1152,64]
    const float* W = (const float*)d_in[1];     // [1152,32,64,64]
    const float* bias = (const float*)d_in[2];  // [1,1152,32,1]
    float* out = (float*)d_out;                 // [32,32,64]

    zero_kernel<<<SV / 256, 256>>>();
    bias_softmax_kernel<<<IC, 32>>>(bias);
    gemm_kernel<<<dim3(NC / CGRP, IC / ICH), 64>>>(x, W);
    squash_kernel<<<BB * NC, 32>>>(0, out);
    route_kernel<<<dim3(IC / RICH, BB), 256>>>(1, bias);
    squash_kernel<<<BB * NC, 32>>>(1, out);
    route_kernel<<<dim3(IC / RICH, BB), 256>>>(2, bias);
    squash_kernel<<<BB * NC, 32>>>(2, out);
}

// round 3
// speedup vs baseline: 1.1782x; 1.1782x over previous
#include <cuda_runtime.h>
#include <cuda_fp16.h>

// CapsuleLayer dynamic routing, GB300 sm_103a.
// B=32, IN_CAPS=1152, P=64, NUM_CAPS=32, Q=64, NUM_ROUTING=3.
//
// hat[b,i,c,q] = sum_p x[b,i,p] * W[i,c,p,q]   (stored fp16, 151 MB)
// r0: c0[i,c]=softmax_c(bias) is batch-independent -> S0 accumulated inside GEMM (fp32 exact)
// r1: b1 = bias + <hat,v0>_q ; S1 = sum_i softmax_c(b1)*hat ; v1=squash(S1)
// r2: b2 = bias + <hat,v0+v1>_q ; S2 = ... ; out = squash(S2)

#define BB 32
#define IC 1152
#define PP 64
#define NC 32
#define QQ 64
#define HAT_ELEMS (BB * IC * NC * QQ)
#define SV (BB * NC * QQ)

// ---------------- device scratch ----------------
__device__ __align__(16) __half g_hat[HAT_ELEMS];   // 151 MB
__device__ __align__(16) float g_S0[SV];
__device__ __align__(16) float g_S1[SV];
__device__ __align__(16) float g_S2[SV];
__device__ __align__(16) float g_v0[SV];
__device__ __align__(16) float g_v01[SV];
__device__ __align__(16) float g_c0[IC * NC];

// ---------------- packed f32x2 + cp.async helpers ----------------
__device__ __forceinline__ unsigned long long pack2(float x, float y) {
    unsigned long long r;
    asm("mov.b64 %0, {%1, %2};" : "=l"(r)
        : "r"(__float_as_uint(x)), "r"(__float_as_uint(y)));
    return r;
}
__device__ __forceinline__ float2 unpack2(unsigned long long v) {
    unsigned int lo, hi;
    asm("mov.b64 {%0, %1}, %2;" : "=r"(lo), "=r"(hi) : "l"(v));
    return make_float2(__uint_as_float(lo), __uint_as_float(hi));
}
__device__ __forceinline__ unsigned int h2_as_u32(__half2 h) {
    union { __half2 h; unsigned int u; } cvt;
    cvt.h = h;
    return cvt.u;
}
#define FMA2(d, a_, b_, c_) \
    asm("fma.rn.f32x2 %0, %1, %2, %3;" : "=l"(d) : "l"(a_), "l"(b_), "l"(c_))

__device__ __forceinline__ void cp16(const void* smem_dst, const void* gmem_src) {
    unsigned int s = (unsigned int)__cvta_generic_to_shared(smem_dst);
    asm volatile("cp.async.cg.shared.global [%0], [%1], 16;" :: "r"(s), "l"(gmem_src));
}
__device__ __forceinline__ void cp_commit() {
    asm volatile("cp.async.commit_group;");
}
template <int N>
__device__ __forceinline__ void cp_wait() {
    asm volatile("cp.async.wait_group %0;" :: "n"(N));
}

// ---------------- prep kernels ----------------
__global__ void zero_kernel() {
    int idx = blockIdx.x * blockDim.x + threadIdx.x;
    if (idx < SV) {
        g_S0[idx] = 0.f;
        g_S1[idx] = 0.f;
        g_S2[idx] = 0.f;
    }
}

__global__ void bias_softmax_kernel(const float* __restrict__ bias) {
    int i = blockIdx.x;
    int lane = threadIdx.x;
    float bv = bias[i * NC + lane];
    float m = bv;
#pragma unroll
    for (int o = 16; o > 0; o >>= 1)
        m = fmaxf(m, __shfl_xor_sync(0xffffffffu, m, o));
    float e = __expf(bv - m);
    float se = e;
#pragma unroll
    for (int o = 16; o > 0; o >>= 1)
        se += __shfl_xor_sync(0xffffffffu, se, o);
    g_c0[i * NC + lane] = e / se;
}

// ---------------- GEMM: hat (fp16) + S0 accumulation, cp.async pipelined ----
// Grid (16, 36), 128 threads. CTA tile: 32 b x 128 n (2 capsules), 32 i.
// Thread tile: 4 b x 8 q (4 f32x2 pairs).
#define CGRP 2
#define ICH 32
#define WSROW 132  // 128 + 4 pad (528 B rows, 16B aligned)
#define WS_FLOATS (PP * WSROW)       // 8448
#define XS_FLOATS (BB * PP)          // 2048
#define GEMM_SMEM_BYTES ((2 * WS_FLOATS + 2 * XS_FLOATS) * 4)  // 83968

__device__ __forceinline__ void gemm_prefetch(float* ws, float* xs,
                                              const float* __restrict__ x,
                                              const float* __restrict__ W,
                                              int i, int cpair, int tid) {
    const float4* wsrc = (const float4*)(W + ((size_t)i * NC + cpair * CGRP) * PP * QQ);
#pragma unroll
    for (int k = 0; k < 16; k++) {
        int j4 = tid + 128 * k;
        int clw = j4 >> 10;
        int p = (j4 >> 4) & 63;
        int q4 = j4 & 15;
        cp16(ws + p * WSROW + clw * QQ + q4 * 4, wsrc + j4);
    }
#pragma unroll
    for (int k = 0; k < 4; k++) {
        int j = tid + 128 * k;  // [0,512)
        int b = j >> 4;
        int p4 = j & 15;
        cp16(xs + b * PP + p4 * 4, x + ((size_t)b * IC + i) * PP + p4 * 4);
    }
}

__global__ __launch_bounds__(128, 2) void gemm_kernel(const float* __restrict__ x,
                                                      const float* __restrict__ W) {
    extern __shared__ __align__(16) float smem[];
    float* ws0 = smem;
    float* ws1 = smem + WS_FLOATS;
    float* xs0 = smem + 2 * WS_FLOATS;
    float* xs1 = xs0 + XS_FLOATS;

    int tid = threadIdx.x;
    int tn = tid & 15;
    int tm = tid >> 4;  // 0..7
    int cpair = blockIdx.x;
    int i0 = blockIdx.y * ICH;
    int cl = tn >> 3;
    int q0 = (tn & 7) << 3;
    int cg = cpair * CGRP + cl;
    int n0 = cl * QQ + q0;

    unsigned long long s0acc[4][4];
#pragma unroll
    for (int k = 0; k < 4; k++)
#pragma unroll
        for (int j = 0; j < 4; j++) s0acc[k][j] = 0ULL;

    gemm_prefetch(ws0, xs0, x, W, i0, cpair, tid);
    cp_commit();

    for (int ii = 0; ii < ICH; ii++) {
        int i = i0 + ii;
        cp_wait<0>();
        __syncthreads();
        if (ii + 1 < ICH) {
            float* wsn = ((ii + 1) & 1) ? ws1 : ws0;
            float* xsn = ((ii + 1) & 1) ? xs1 : xs0;
            gemm_prefetch(wsn, xsn, x, W, i + 1, cpair, tid);
            cp_commit();
        }
        const float* wsc = (ii & 1) ? ws1 : ws0;
        const float* xsc = (ii & 1) ? xs1 : xs0;

        unsigned long long acc[4][4];
#pragma unroll
        for (int k = 0; k < 4; k++)
#pragma unroll
            for (int j = 0; j < 4; j++) acc[k][j] = 0ULL;

#pragma unroll 4
        for (int p4 = 0; p4 < 16; p4++) {
            float4 xv[4];
#pragma unroll
            for (int k = 0; k < 4; k++)
                xv[k] = *(const float4*)(xsc + (tm * 4 + k) * PP + p4 * 4);
#pragma unroll
            for (int pp = 0; pp < 4; pp++) {
                const float* wr = wsc + (p4 * 4 + pp) * WSROW + n0;
                ulonglong2 w01 = *(const ulonglong2*)wr;
                ulonglong2 w23 = *(const ulonglong2*)(wr + 4);
#pragma unroll
                for (int k = 0; k < 4; k++) {
                    float av = ((const float*)&xv[k])[pp];
                    unsigned long long a2 = pack2(av, av);
                    FMA2(acc[k][0], a2, w01.x, acc[k][0]);
                    FMA2(acc[k][1], a2, w01.y, acc[k][1]);
                    FMA2(acc[k][2], a2, w23.x, acc[k][2]);
                    FMA2(acc[k][3], a2, w23.y, acc[k][3]);
                }
            }
        }

        // store hat (fp16) + accumulate c0-weighted S0 partial (fp32)
        float wgt = g_c0[i * NC + cg];
        unsigned long long w2 = pack2(wgt, wgt);
#pragma unroll
        for (int k = 0; k < 4; k++) {
            int b = tm * 4 + k;
            float2 f0 = unpack2(acc[k][0]);
            float2 f1 = unpack2(acc[k][1]);
            float2 f2 = unpack2(acc[k][2]);
            float2 f3 = unpack2(acc[k][3]);
            uint4 st;
            st.x = h2_as_u32(__floats2half2_rn(f0.x, f0.y));
            st.y = h2_as_u32(__floats2half2_rn(f1.x, f1.y));
            st.z = h2_as_u32(__floats2half2_rn(f2.x, f2.y));
            st.w = h2_as_u32(__floats2half2_rn(f3.x, f3.y));
            *(uint4*)(g_hat + (((size_t)b * IC + i) * NC + cg) * QQ + q0) = st;
#pragma unroll
            for (int j = 0; j < 4; j++)
                FMA2(s0acc[k][j], w2, acc[k][j], s0acc[k][j]);
        }
    }

#pragma unroll
    for (int k = 0; k < 4; k++) {
        int b = tm * 4 + k;
        float* sp = g_S0 + ((size_t)b * NC + cg) * QQ + q0;
#pragma unroll
        for (int j = 0; j < 4; j++) {
            float2 f = unpack2(s0acc[k][j]);
            atomicAdd(sp + j * 2, f.x);
            atomicAdd(sp + j * 2 + 1, f.y);
        }
    }
}

// ---------------- routing pass (rounds 1, 2), fp16 hat, pipelined ----------
#define RICH 36

__global__ __launch_bounds__(256) void route_kernel(int round,
                                                    const float* __restrict__ bias) {
    __shared__ __align__(16) float vsh[NC * QQ];          // 8 KB
    __shared__ __align__(16) __half hb[2][NC * QQ];       // 2 x 4 KB
    __shared__ float tb[NC];
    __shared__ float bsh[RICH * NC];                      // 4.6 KB

    const float* vin = (round == 1) ? g_v0 : g_v01;
    float* Sout = (round == 1) ? g_S1 : g_S2;

    int tid = threadIdx.x;
    int lane = tid & 31;
    int warp = tid >> 5;
    int b = blockIdx.y;
    int i0 = blockIdx.x * RICH;

    for (int j = tid; j < NC * QQ; j += 256) vsh[j] = vin[b * (NC * QQ) + j];
    for (int j = tid; j < RICH * NC; j += 256) bsh[j] = bias[i0 * NC + j];

    // prefetch tile 0
    cp16(hb[0] + tid * 8, g_hat + ((size_t)b * IC + i0) * (NC * QQ) + tid * 8);
    cp_commit();

    float racc[8];
#pragma unroll
    for (int j = 0; j < 8; j++) racc[j] = 0.f;

    int c = tid >> 3, jj = tid & 7;
    const float2* v2 = (const float2*)vsh;

    for (int ii = 0; ii < RICH; ii++) {
        cp_wait<0>();
        __syncthreads();
        if (ii + 1 < RICH) {
            cp16(hb[(ii + 1) & 1] + tid * 8,
                 g_hat + ((size_t)b * IC + i0 + ii + 1) * (NC * QQ) + tid * 8);
            cp_commit();
        }
        const __half2* hp = (const __half2*)hb[ii & 1];  // 1024 half2

        // logits: 8 threads per capsule
        float s = 0.f;
#pragma unroll
        for (int m = 0; m < 4; m++) {
            float2 h = __half22float2(hp[c * 32 + jj * 4 + m]);
            float2 v = v2[c * 32 + jj * 4 + m];
            s += h.x * v.x + h.y * v.y;
        }
        s += __shfl_down_sync(0xffffffffu, s, 4);
        s += __shfl_down_sync(0xffffffffu, s, 2);
        s += __shfl_down_sync(0xffffffffu, s, 1);
        if (jj == 0) tb[c] = bsh[ii * NC + c] + s;
        __syncthreads();

        // softmax, redundantly per warp (lane holds capsule=lane weight)
        float t = tb[lane];
        float m = t;
#pragma unroll
        for (int o = 16; o > 0; o >>= 1)
            m = fmaxf(m, __shfl_xor_sync(0xffffffffu, m, o));
        float e = __expf(t - m);
        float se = e;
#pragma unroll
        for (int o = 16; o > 0; o >>= 1)
            se += __shfl_xor_sync(0xffffffffu, se, o);
        float w = e / se;

        // weighted accumulation in registers
#pragma unroll
        for (int k = 0; k < 4; k++) {
            int idx2 = tid + 256 * k;                        // c = 8k + warp
            float wc = __shfl_sync(0xffffffffu, w, 8 * k + warp);
            float2 h = __half22float2(hp[idx2]);
            racc[2 * k] += wc * h.x;
            racc[2 * k + 1] += wc * h.y;
        }
    }

#pragma unroll
    for (int k = 0; k < 4; k++) {
        int idx2 = tid + 256 * k;
        atomicAdd(&Sout[b * (NC * QQ) + idx2 * 2], racc[2 * k]);
        atomicAdd(&Sout[b * (NC * QQ) + idx2 * 2 + 1], racc[2 * k + 1]);
    }
}

// ---------------- squash ----------------
__global__ void squash_kernel(int mode, float* __restrict__ dout) {
    const float* S = (mode == 0) ? g_S0 : (mode == 1) ? g_S1 : g_S2;
    int vec = blockIdx.x;  // b*NC + c
    int lane = threadIdx.x;
    float x0 = S[vec * QQ + lane];
    float x1 = S[vec * QQ + 32 + lane];
    float ss = x0 * x0 + x1 * x1;
#pragma unroll
    for (int o = 16; o > 0; o >>= 1)
        ss += __shfl_xor_sync(0xffffffffu, ss, o);
    float sc = (ss > 0.f) ? (ss / (1.f + ss)) * rsqrtf(ss) : 0.f;
    float o0 = sc * x0, o1 = sc * x1;
    if (mode == 0) {
        g_v0[vec * QQ + lane] = o0;
        g_v0[vec * QQ + 32 + lane] = o1;
    } else if (mode == 1) {
        g_v01[vec * QQ + lane] = g_v0[vec * QQ + lane] + o0;
        g_v01[vec * QQ + 32 + lane] = g_v0[vec * QQ + 32 + lane] + o1;
    } else {
        dout[vec * QQ + lane] = o0;
        dout[vec * QQ + 32 + lane] = o1;
    }
}

// ---------------- launch ----------------
extern "C" void kernel_launch(void* const* d_in, const int* in_sizes, int n_in,
                              void* d_out, int out_size) {
    const float* x = (const float*)d_in[0];     // [32,1152,64]
    const float* W = (const float*)d_in[1];     // [1152,32,64,64]
    const float* bias = (const float*)d_in[2];  // [1,1152,32,1]
    float* out = (float*)d_out;                 // [32,32,64]

    static int smem_set = 0;
    if (!smem_set) {
        cudaFuncSetAttribute(gemm_kernel, cudaFuncAttributeMaxDynamicSharedMemorySize,
                             GEMM_SMEM_BYTES);
        smem_set = 1;
    }

    zero_kernel<<<SV / 256, 256>>>();
    bias_softmax_kernel<<<IC, 32>>>(bias);
    gemm_kernel<<<dim3(NC / CGRP, IC / ICH), 128, GEMM_SMEM_BYTES>>>(x, W);
    squash_kernel<<<BB * NC, 32>>>(0, out);
    route_kernel<<<dim3(IC / RICH, BB), 256>>>(1, bias);
    squash_kernel<<<BB * NC, 32>>>(1, out);
    route_kernel<<<dim3(IC / RICH, BB), 256>>>(2, bias);
    squash_kernel<<<BB * NC, 32>>>(2, out);
}

// round 4
// speedup vs baseline: 1.5511x; 1.3165x over previous
#include <cuda_runtime.h>
#include <cuda_fp16.h>

// CapsuleLayer dynamic routing, GB300 sm_103a.
// B=32, IN_CAPS=1152, P=64, NUM_CAPS=32, Q=64, NUM_ROUTING=3.
//
// hat[b,i,c,q] = sum_p x[b,i,p] * W[i,c,p,q]   (stored fp16, 151 MB)
// r0: c0 = softmax_c(bias) batch-independent -> S0 accumulated inside GEMM (fp32)
// r1: b1 = bias + <hat,v0>_q ; S1 = sum_i softmax_c(b1)*hat ; v1=squash(S1)
// r2: b2 = bias + <hat,v0+v1>_q ; S2 = ... ; out = squash(S2)

#define BB 32
#define IC 1152
#define PP 64
#define NC 32
#define QQ 64
#define HAT_ELEMS (BB * IC * NC * QQ)
#define SV (BB * NC * QQ)

// ---------------- device scratch ----------------
__device__ __align__(16) __half g_hat[HAT_ELEMS];   // 151 MB
__device__ __align__(16) float g_S0[SV];
__device__ __align__(16) float g_S1[SV];
__device__ __align__(16) float g_S2[SV];
__device__ __align__(16) float g_v0[SV];
__device__ __align__(16) float g_v01[SV];
__device__ __align__(16) float g_c0[IC * NC];

// ---------------- packed f32x2 + cp.async helpers ----------------
__device__ __forceinline__ unsigned long long pack2(float x, float y) {
    unsigned long long r;
    asm("mov.b64 %0, {%1, %2};" : "=l"(r)
        : "r"(__float_as_uint(x)), "r"(__float_as_uint(y)));
    return r;
}
__device__ __forceinline__ float2 unpack2(unsigned long long v) {
    unsigned int lo, hi;
    asm("mov.b64 {%0, %1}, %2;" : "=r"(lo), "=r"(hi) : "l"(v));
    return make_float2(__uint_as_float(lo), __uint_as_float(hi));
}
__device__ __forceinline__ unsigned int h2_as_u32(__half2 h) {
    union { __half2 h; unsigned int u; } cvt;
    cvt.h = h;
    return cvt.u;
}
#define FMA2(d, a_, b_, c_) \
    asm("fma.rn.f32x2 %0, %1, %2, %3;" : "=l"(d) : "l"(a_), "l"(b_), "l"(c_))

__device__ __forceinline__ void cp16(const void* smem_dst, const void* gmem_src) {
    unsigned int s = (unsigned int)__cvta_generic_to_shared(smem_dst);
    asm volatile("cp.async.cg.shared.global [%0], [%1], 16;" :: "r"(s), "l"(gmem_src));
}
__device__ __forceinline__ void cp_commit() {
    asm volatile("cp.async.commit_group;");
}
template <int N>
__device__ __forceinline__ void cp_wait() {
    asm volatile("cp.async.wait_group %0;" :: "n"(N));
}

// ---------------- prep kernels ----------------
__global__ void zero_kernel() {
    int idx = blockIdx.x * blockDim.x + threadIdx.x;
    if (idx < SV) {
        g_S0[idx] = 0.f;
        g_S1[idx] = 0.f;
        g_S2[idx] = 0.f;
    }
}

__global__ void pad_kernel() {}  // profiler alignment only

__global__ void bias_softmax_kernel(const float* __restrict__ bias) {
    int i = blockIdx.x;
    int lane = threadIdx.x;
    float bv = bias[i * NC + lane];
    float m = bv;
#pragma unroll
    for (int o = 16; o > 0; o >>= 1)
        m = fmaxf(m, __shfl_xor_sync(0xffffffffu, m, o));
    float e = __expf(bv - m);
    float se = e;
#pragma unroll
    for (int o = 16; o > 0; o >>= 1)
        se += __shfl_xor_sync(0xffffffffu, se, o);
    g_c0[i * NC + lane] = e / se;
}

// ---------------- GEMM: hat (fp16) + S0 accumulation, cp.async pipelined ----
// Grid (32, 36), 64 threads. CTA tile: 32 b x 64 q (1 capsule), 32 i-chunk.
// Thread tile: 8 b x 4 q (2 f32x2 q-pairs). 4 CTAs/SM.
#define ICH 32
#define WS_FLOATS (PP * QQ)          // 4096 (16 KB), layout [p][q], q contiguous
#define XS_FLOATS (BB * PP)          // 2048 (8 KB)
#define GEMM_SMEM_BYTES ((2 * WS_FLOATS + 2 * XS_FLOATS) * 4)  // 49152

__device__ __forceinline__ void gemm_prefetch(float* ws, float* xs,
                                              const float* __restrict__ x,
                                              const float* __restrict__ W,
                                              int i, int c, int tid) {
    const float4* wsrc = (const float4*)(W + ((size_t)i * NC + c) * (PP * QQ));
    float4* wdst4 = (float4*)ws;
#pragma unroll
    for (int k = 0; k < 16; k++) {
        int j4 = tid + 64 * k;  // [0,1024)
        cp16(wdst4 + j4, wsrc + j4);
    }
#pragma unroll
    for (int k = 0; k < 8; k++) {
        int j = tid + 64 * k;  // [0,512)
        int b = j >> 4;
        int p4 = j & 15;
        cp16(xs + b * PP + p4 * 4, x + ((size_t)b * IC + i) * PP + p4 * 4);
    }
}

__global__ __launch_bounds__(64, 4) void gemm_kernel(const float* __restrict__ x,
                                                     const float* __restrict__ W) {
    extern __shared__ __align__(16) float smem[];
    float* ws0 = smem;
    float* ws1 = smem + WS_FLOATS;
    float* xs0 = smem + 2 * WS_FLOATS;
    float* xs1 = xs0 + XS_FLOATS;

    int tid = threadIdx.x;
    int tn = tid & 15;      // q position
    int tm = tid >> 4;      // 0..3, b-group of 8
    int c = blockIdx.x;     // capsule
    int i0 = blockIdx.y * ICH;
    int q0 = tn * 4;

    unsigned long long s0acc[8][2];
#pragma unroll
    for (int k = 0; k < 8; k++) {
        s0acc[k][0] = 0ULL;
        s0acc[k][1] = 0ULL;
    }

    gemm_prefetch(ws0, xs0, x, W, i0, c, tid);
    cp_commit();

    for (int ii = 0; ii < ICH; ii++) {
        int i = i0 + ii;
        cp_wait<0>();
        __syncthreads();
        if (ii + 1 < ICH) {
            float* wsn = ((ii + 1) & 1) ? ws1 : ws0;
            float* xsn = ((ii + 1) & 1) ? xs1 : xs0;
            gemm_prefetch(wsn, xsn, x, W, i + 1, c, tid);
        }
        cp_commit();
        const float* wsc = (ii & 1) ? ws1 : ws0;
        const float* xsc = (ii & 1) ? xs1 : xs0;

        unsigned long long acc[8][2];
#pragma unroll
        for (int k = 0; k < 8; k++) {
            acc[k][0] = 0ULL;
            acc[k][1] = 0ULL;
        }

#pragma unroll 2
        for (int p4 = 0; p4 < 16; p4++) {
            float4 xv[8];
#pragma unroll
            for (int k = 0; k < 8; k++)
                xv[k] = *(const float4*)(xsc + (tm * 8 + k) * PP + p4 * 4);
#pragma unroll
            for (int pp = 0; pp < 4; pp++) {
                // conflict-free: lane offsets q0*4 = 0,16,...,240 B
                ulonglong2 wq =
                    *(const ulonglong2*)(wsc + (p4 * 4 + pp) * QQ + q0);
#pragma unroll
                for (int k = 0; k < 8; k++) {
                    float av = ((const float*)&xv[k])[pp];
                    unsigned long long a2 = pack2(av, av);
                    FMA2(acc[k][0], a2, wq.x, acc[k][0]);
                    FMA2(acc[k][1], a2, wq.y, acc[k][1]);
                }
            }
        }

        // store hat (fp16) + accumulate c0-weighted S0 partial (fp32)
        float wgt = g_c0[i * NC + c];
        unsigned long long w2 = pack2(wgt, wgt);
#pragma unroll
        for (int k = 0; k < 8; k++) {
            int b = tm * 8 + k;
            float2 f0 = unpack2(acc[k][0]);
            float2 f1 = unpack2(acc[k][1]);
            uint2 st;
            st.x = h2_as_u32(__floats2half2_rn(f0.x, f0.y));
            st.y = h2_as_u32(__floats2half2_rn(f1.x, f1.y));
            *(uint2*)(g_hat + (((size_t)b * IC + i) * NC + c) * QQ + q0) = st;
            FMA2(s0acc[k][0], w2, acc[k][0], s0acc[k][0]);
            FMA2(s0acc[k][1], w2, acc[k][1], s0acc[k][1]);
        }
    }

#pragma unroll
    for (int k = 0; k < 8; k++) {
        int b = tm * 8 + k;
        float* sp = g_S0 + ((size_t)b * NC + c) * QQ + q0;
        float2 f0 = unpack2(s0acc[k][0]);
        float2 f1 = unpack2(s0acc[k][1]);
        atomicAdd(sp + 0, f0.x);
        atomicAdd(sp + 1, f0.y);
        atomicAdd(sp + 2, f1.x);
        atomicAdd(sp + 3, f1.y);
    }
}

// ---------------- routing pass (rounds 1, 2), fp16 hat, depth-2 pipeline ----
#define RICH 36

__global__ __launch_bounds__(256) void route_kernel(int round,
                                                    const float* __restrict__ bias) {
    __shared__ __align__(16) float vsh[NC * QQ];          // 8 KB
    __shared__ __align__(16) __half hb[3][NC * QQ];       // 3 x 4 KB
    __shared__ float tb[NC];
    __shared__ float bsh[RICH * NC];                      // 4.6 KB

    const float* vin = (round == 1) ? g_v0 : g_v01;
    float* Sout = (round == 1) ? g_S1 : g_S2;

    int tid = threadIdx.x;
    int lane = tid & 31;
    int warp = tid >> 5;
    int b = blockIdx.y;
    int i0 = blockIdx.x * RICH;

    for (int j = tid; j < NC * QQ; j += 256) vsh[j] = vin[b * (NC * QQ) + j];
    for (int j = tid; j < RICH * NC; j += 256) bsh[j] = bias[i0 * NC + j];

    // prefetch tiles 0 and 1 (separate commit groups)
    cp16(hb[0] + tid * 8, g_hat + ((size_t)b * IC + i0) * (NC * QQ) + tid * 8);
    cp_commit();
    cp16(hb[1] + tid * 8, g_hat + ((size_t)b * IC + i0 + 1) * (NC * QQ) + tid * 8);
    cp_commit();

    float racc[8];
#pragma unroll
    for (int j = 0; j < 8; j++) racc[j] = 0.f;

    int c = tid >> 3, jj = tid & 7;
    const float2* v2 = (const float2*)vsh;

    for (int ii = 0; ii < RICH; ii++) {
        cp_wait<1>();   // tile ii ready (tile ii+1 may still be in flight)
        __syncthreads();
        if (ii + 2 < RICH) {
            int buf = (ii + 2) % 3;
            cp16(hb[buf] + tid * 8,
                 g_hat + ((size_t)b * IC + i0 + ii + 2) * (NC * QQ) + tid * 8);
        }
        cp_commit();    // empty group at tail keeps wait<1> semantics correct
        const __half2* hp = (const __half2*)hb[ii % 3];  // 1024 half2

        // logits: 8 threads per capsule
        float s = 0.f;
#pragma unroll
        for (int m = 0; m < 4; m++) {
            float2 h = __half22float2(hp[c * 32 + jj * 4 + m]);
            float2 v = v2[c * 32 + jj * 4 + m];
            s += h.x * v.x + h.y * v.y;
        }
        s += __shfl_down_sync(0xffffffffu, s, 4);
        s += __shfl_down_sync(0xffffffffu, s, 2);
        s += __shfl_down_sync(0xffffffffu, s, 1);
        if (jj == 0) tb[c] = bsh[ii * NC + c] + s;
        __syncthreads();

        // softmax, redundantly per warp (lane holds capsule=lane weight)
        float t = tb[lane];
        float m = t;
#pragma unroll
        for (int o = 16; o > 0; o >>= 1)
            m = fmaxf(m, __shfl_xor_sync(0xffffffffu, m, o));
        float e = __expf(t - m);
        float se = e;
#pragma unroll
        for (int o = 16; o > 0; o >>= 1)
            se += __shfl_xor_sync(0xffffffffu, se, o);
        float w = e / se;

        // weighted accumulation in registers
#pragma unroll
        for (int k = 0; k < 4; k++) {
            int idx2 = tid + 256 * k;                        // c = 8k + warp
            float wc = __shfl_sync(0xffffffffu, w, 8 * k + warp);
            float2 h = __half22float2(hp[idx2]);
            racc[2 * k] += wc * h.x;
            racc[2 * k + 1] += wc * h.y;
        }
    }

#pragma unroll
    for (int k = 0; k < 4; k++) {
        int idx2 = tid + 256 * k;
        atomicAdd(&Sout[b * (NC * QQ) + idx2 * 2], racc[2 * k]);
        atomicAdd(&Sout[b * (NC * QQ) + idx2 * 2 + 1], racc[2 * k + 1]);
    }
}

// ---------------- squash ----------------
__global__ void squash_kernel(int mode, float* __restrict__ dout) {
    const float* S = (mode == 0) ? g_S0 : (mode == 1) ? g_S1 : g_S2;
    int vec = blockIdx.x;  // b*NC + c
    int lane = threadIdx.x;
    float x0 = S[vec * QQ + lane];
    float x1 = S[vec * QQ + 32 + lane];
    float ss = x0 * x0 + x1 * x1;
#pragma unroll
    for (int o = 16; o > 0; o >>= 1)
        ss += __shfl_xor_sync(0xffffffffu, ss, o);
    float sc = (ss > 0.f) ? (ss / (1.f + ss)) * rsqrtf(ss) : 0.f;
    float o0 = sc * x0, o1 = sc * x1;
    if (mode == 0) {
        g_v0[vec * QQ + lane] = o0;
        g_v0[vec * QQ + 32 + lane] = o1;
    } else if (mode == 1) {
        g_v01[vec * QQ + lane] = g_v0[vec * QQ + lane] + o0;
        g_v01[vec * QQ + 32 + lane] = g_v0[vec * QQ + 32 + lane] + o1;
    } else {
        dout[vec * QQ + lane] = o0;
        dout[vec * QQ + 32 + lane] = o1;
    }
}

// ---------------- launch ----------------
extern "C" void kernel_launch(void* const* d_in, const int* in_sizes, int n_in,
                              void* d_out, int out_size) {
    const float* x = (const float*)d_in[0];     // [32,1152,64]
    const float* W = (const float*)d_in[1];     // [1152,32,64,64]
    const float* bias = (const float*)d_in[2];  // [1,1152,32,1]
    float* out = (float*)d_out;                 // [32,32,64]

    static int smem_set = 0;
    if (!smem_set) {
        cudaFuncSetAttribute(gemm_kernel, cudaFuncAttributeMaxDynamicSharedMemorySize,
                             GEMM_SMEM_BYTES);
        smem_set = 1;
    }

    zero_kernel<<<SV / 256, 256>>>();          // launch 1
    bias_softmax_kernel<<<IC, 32>>>(bias);     // launch 2
    pad_kernel<<<1, 1>>>();                    // launch 3
    pad_kernel<<<1, 1>>>();                    // launch 4
    pad_kernel<<<1, 1>>>();                    // launch 5
    gemm_kernel<<<dim3(NC, IC / ICH), 64, GEMM_SMEM_BYTES>>>(x, W);  // launch 6 -> ncu
    squash_kernel<<<BB * NC, 32>>>(0, out);
    route_kernel<<<dim3(IC / RICH, BB), 256>>>(1, bias);
    squash_kernel<<<BB * NC, 32>>>(1, out);
    route_kernel<<<dim3(IC / RICH, BB), 256>>>(2, bias);
    squash_kernel<<<BB * NC, 32>>>(2, out);
}

// round 5
// speedup vs baseline: 1.9548x; 1.2602x over previous
#include <cuda_runtime.h>
#include <cuda_fp16.h>

// CapsuleLayer dynamic routing, GB300 sm_103a.
// B=32, IN_CAPS=1152, P=64, NUM_CAPS=32, Q=64, NUM_ROUTING=3.
//
// hat[b,i,c,q] = sum_p x[b,i,p] * W[i,c,p,q]   (tf32 tensor-core, stored fp16)
// r0: c0 = softmax_c(bias) batch-independent -> S0 accumulated inside GEMM (fp32)
// r1: b1 = bias + <hat,v0>_q ; S1 = sum_i softmax_c(b1)*hat ; v1=squash(S1)
// r2: b2 = bias + <hat,v0+v1>_q ; S2 = ... ; out = squash(S2)

#define BB 32
#define IC 1152
#define PP 64
#define NC 32
#define QQ 64
#define HAT_ELEMS (BB * IC * NC * QQ)
#define SV (BB * NC * QQ)

// ---------------- device scratch ----------------
__device__ __align__(16) __half g_hat[HAT_ELEMS];   // 151 MB
__device__ __align__(16) float g_S0[SV];
__device__ __align__(16) float g_S1[SV];
__device__ __align__(16) float g_S2[SV];
__device__ __align__(16) float g_v0[SV];
__device__ __align__(16) float g_v01[SV];
__device__ __align__(16) float g_c0[IC * NC];

// ---------------- helpers ----------------
__device__ __forceinline__ unsigned int fu(float f) { return __float_as_uint(f); }

__device__ __forceinline__ void cp16(const void* smem_dst, const void* gmem_src) {
    unsigned int s = (unsigned int)__cvta_generic_to_shared(smem_dst);
    asm volatile("cp.async.cg.shared.global [%0], [%1], 16;" :: "r"(s), "l"(gmem_src));
}
__device__ __forceinline__ void cp_commit() {
    asm volatile("cp.async.commit_group;");
}
template <int N>
__device__ __forceinline__ void cp_wait() {
    asm volatile("cp.async.wait_group %0;" :: "n"(N));
}

// tf32 m16n8k8: D += A*B. A row-major [16x8], B col-major [8x8], fp32 accum.
#define MMA_TF32(D, A, B0, B1)                                            \
    asm volatile(                                                          \
        "mma.sync.aligned.m16n8k8.row.col.f32.tf32.tf32.f32 "              \
        "{%0,%1,%2,%3},{%4,%5,%6,%7},{%8,%9},{%0,%1,%2,%3};"               \
        : "+f"((D)[0]), "+f"((D)[1]), "+f"((D)[2]), "+f"((D)[3])           \
        : "r"(fu((A)[0])), "r"(fu((A)[1])), "r"(fu((A)[2])), "r"(fu((A)[3])), \
          "r"(fu(B0)), "r"(fu(B1)))

// ---------------- prep kernels ----------------
__global__ void zero_kernel() {
    int idx = blockIdx.x * blockDim.x + threadIdx.x;
    if (idx < SV) {
        g_S0[idx] = 0.f;
        g_S1[idx] = 0.f;
        g_S2[idx] = 0.f;
    }
}

__global__ void bias_softmax_kernel(const float* __restrict__ bias) {
    int i = blockIdx.x;
    int lane = threadIdx.x;
    float bv = bias[i * NC + lane];
    float m = bv;
#pragma unroll
    for (int o = 16; o > 0; o >>= 1)
        m = fmaxf(m, __shfl_xor_sync(0xffffffffu, m, o));
    float e = __expf(bv - m);
    float se = e;
#pragma unroll
    for (int o = 16; o > 0; o >>= 1)
        se += __shfl_xor_sync(0xffffffffu, se, o);
    g_c0[i * NC + lane] = e / se;
}

// ---------------- GEMM (tf32 tensor core): hat (fp16) + S0 -----------------
// Grid (16 cpairs, 36 iblocks), 128 threads (4 warps), 2 CTAs/SM.
// Per i: A = x[32b x 64p], B = W[i, 2 capsules] as [64k x 128n]. Warp w owns
// n-slice n0=w*32 (one capsule each). 8 k-steps of m16n8k8.
#define ICH 32
#define WS_STRIDE 136   // floats per k-row; 136 % 32 == 8 -> bank = 8k+n, conflict-free
#define XS_STRIDE 68    // floats per b-row; 68 % 32 == 4  -> bank = 4b+p, conflict-free
#define WS_FLOATS (PP * WS_STRIDE)   // 8704
#define XS_FLOATS (BB * XS_STRIDE)   // 2176
#define GEMM_SMEM_BYTES ((2 * WS_FLOATS + 2 * XS_FLOATS) * 4)  // 87040

__device__ __forceinline__ void gemm_prefetch(float* ws, float* xs,
                                              const float* __restrict__ x,
                                              const float* __restrict__ W,
                                              int i, int cpair, int tid) {
    // W block: 2 capsules x 64p x 64q fp32 = 2048 float4
    const float4* wsrc = (const float4*)(W + ((size_t)i * NC + cpair * 2) * (PP * QQ));
#pragma unroll
    for (int k = 0; k < 16; k++) {
        int j4 = tid + 128 * k;          // [0,2048)
        int cl = j4 >> 10;               // capsule within pair
        int p = (j4 >> 4) & 63;
        int q4 = j4 & 15;
        cp16(ws + p * WS_STRIDE + cl * QQ + q4 * 4, wsrc + j4);
    }
    // x block: 32b x 64p = 512 float4
#pragma unroll
    for (int k = 0; k < 4; k++) {
        int j = tid + 128 * k;           // [0,512)
        int b = j >> 4;
        int p4 = j & 15;
        cp16(xs + b * XS_STRIDE + p4 * 4, x + ((size_t)b * IC + i) * PP + p4 * 4);
    }
}

__global__ __launch_bounds__(128, 2) void gemm_kernel(const float* __restrict__ x,
                                                      const float* __restrict__ W) {
    extern __shared__ __align__(16) float smem[];
    float* ws0 = smem;
    float* ws1 = smem + WS_FLOATS;
    float* xs0 = smem + 2 * WS_FLOATS;
    float* xs1 = xs0 + XS_FLOATS;

    int tid = threadIdx.x;
    int warp = tid >> 5;
    int lane = tid & 31;
    int g = lane >> 2;      // group 0..7
    int tig = lane & 3;     // 0..3
    int cpair = blockIdx.x;
    int i0 = blockIdx.y * ICH;
    int n0 = warp * 32;             // slice within 128-wide N
    int cl = n0 >> 6;               // capsule-local (warp 0,1 -> 0; 2,3 -> 1)
    int c = cpair * 2 + cl;
    int qbase = (n0 & 63) + tig * 2;  // q of d0/d1 within capsule (nt adds 8*nt)

    float s0[2][4][4];
#pragma unroll
    for (int mt = 0; mt < 2; mt++)
#pragma unroll
        for (int nt = 0; nt < 4; nt++)
#pragma unroll
            for (int j = 0; j < 4; j++) s0[mt][nt][j] = 0.f;

    gemm_prefetch(ws0, xs0, x, W, i0, cpair, tid);
    cp_commit();

    for (int ii = 0; ii < ICH; ii++) {
        int i = i0 + ii;
        cp_wait<0>();
        __syncthreads();
        if (ii + 1 < ICH) {
            float* wsn = ((ii + 1) & 1) ? ws1 : ws0;
            float* xsn = ((ii + 1) & 1) ? xs1 : xs0;
            gemm_prefetch(wsn, xsn, x, W, i + 1, cpair, tid);
        }
        cp_commit();
        const float* wsc = (ii & 1) ? ws1 : ws0;
        const float* xsc = (ii & 1) ? xs1 : xs0;

        float d[2][4][4];
#pragma unroll
        for (int mt = 0; mt < 2; mt++)
#pragma unroll
            for (int nt = 0; nt < 4; nt++)
#pragma unroll
                for (int j = 0; j < 4; j++) d[mt][nt][j] = 0.f;

#pragma unroll
        for (int ks = 0; ks < 8; ks++) {
            // A fragments: a0:(g,k) a1:(g+8,k) a2:(g,k+4) a3:(g+8,k+4)
            float a[2][4];
#pragma unroll
            for (int mt = 0; mt < 2; mt++) {
                int base = (mt * 16 + g) * XS_STRIDE + ks * 8 + tig;
                a[mt][0] = xsc[base];
                a[mt][1] = xsc[base + 8 * XS_STRIDE];
                a[mt][2] = xsc[base + 4];
                a[mt][3] = xsc[base + 8 * XS_STRIDE + 4];
            }
#pragma unroll
            for (int nt = 0; nt < 4; nt++) {
                // B fragments: b0:(k=tig, n=g) b1:(k=tig+4, n=g)
                int bb = (ks * 8 + tig) * WS_STRIDE + n0 + nt * 8 + g;
                float b0 = wsc[bb];
                float b1 = wsc[bb + 4 * WS_STRIDE];
                MMA_TF32(d[0][nt], a[0], b0, b1);
                MMA_TF32(d[1][nt], a[1], b0, b1);
            }
        }

        // epilogue: hat (fp16) + S0 += c0 * d
        float wgt = g_c0[i * NC + c];
#pragma unroll
        for (int mt = 0; mt < 2; mt++) {
#pragma unroll
            for (int nt = 0; nt < 4; nt++) {
                int brow = mt * 16 + g;
                int q = qbase + nt * 8;
                __half2 h01 = __floats2half2_rn(d[mt][nt][0], d[mt][nt][1]);
                __half2 h23 = __floats2half2_rn(d[mt][nt][2], d[mt][nt][3]);
                *(__half2*)(g_hat + (((size_t)brow * IC + i) * NC + c) * QQ + q) = h01;
                *(__half2*)(g_hat + (((size_t)(brow + 8) * IC + i) * NC + c) * QQ + q) = h23;
#pragma unroll
                for (int j = 0; j < 4; j++)
                    s0[mt][nt][j] = fmaf(wgt, d[mt][nt][j], s0[mt][nt][j]);
            }
        }
    }

    // per-CTA partial -> global S0
#pragma unroll
    for (int mt = 0; mt < 2; mt++) {
#pragma unroll
        for (int nt = 0; nt < 4; nt++) {
            int q = qbase + nt * 8;
            int b0r = mt * 16 + g;
            atomicAdd(&g_S0[((size_t)b0r * NC + c) * QQ + q], s0[mt][nt][0]);
            atomicAdd(&g_S0[((size_t)b0r * NC + c) * QQ + q + 1], s0[mt][nt][1]);
            atomicAdd(&g_S0[((size_t)(b0r + 8) * NC + c) * QQ + q], s0[mt][nt][2]);
            atomicAdd(&g_S0[((size_t)(b0r + 8) * NC + c) * QQ + q + 1], s0[mt][nt][3]);
        }
    }
}

// ---------------- routing pass (rounds 1, 2), fp16 hat, depth-2 pipeline ----
#define RICH 36

__global__ __launch_bounds__(256) void route_kernel(int round,
                                                    const float* __restrict__ bias) {
    __shared__ __align__(16) float vsh[NC * QQ];          // 8 KB
    __shared__ __align__(16) __half hb[3][NC * QQ];       // 3 x 4 KB
    __shared__ float tb[NC];
    __shared__ float bsh[RICH * NC];                      // 4.6 KB

    const float* vin = (round == 1) ? g_v0 : g_v01;
    float* Sout = (round == 1) ? g_S1 : g_S2;

    int tid = threadIdx.x;
    int lane = tid & 31;
    int warp = tid >> 5;
    int b = blockIdx.y;
    int i0 = blockIdx.x * RICH;

    for (int j = tid; j < NC * QQ; j += 256) vsh[j] = vin[b * (NC * QQ) + j];
    for (int j = tid; j < RICH * NC; j += 256) bsh[j] = bias[i0 * NC + j];

    cp16(hb[0] + tid * 8, g_hat + ((size_t)b * IC + i0) * (NC * QQ) + tid * 8);
    cp_commit();
    cp16(hb[1] + tid * 8, g_hat + ((size_t)b * IC + i0 + 1) * (NC * QQ) + tid * 8);
    cp_commit();

    float racc[8];
#pragma unroll
    for (int j = 0; j < 8; j++) racc[j] = 0.f;

    int c = tid >> 3, jj = tid & 7;
    const float2* v2 = (const float2*)vsh;

    for (int ii = 0; ii < RICH; ii++) {
        cp_wait<1>();   // tile ii ready
        __syncthreads();
        if (ii + 2 < RICH) {
            int buf = (ii + 2) % 3;
            cp16(hb[buf] + tid * 8,
                 g_hat + ((size_t)b * IC + i0 + ii + 2) * (NC * QQ) + tid * 8);
        }
        cp_commit();
        const __half2* hp = (const __half2*)hb[ii % 3];

        // logits: 8 threads per capsule
        float s = 0.f;
#pragma unroll
        for (int m = 0; m < 4; m++) {
            float2 h = __half22float2(hp[c * 32 + jj * 4 + m]);
            float2 v = v2[c * 32 + jj * 4 + m];
            s += h.x * v.x + h.y * v.y;
        }
        s += __shfl_down_sync(0xffffffffu, s, 4);
        s += __shfl_down_sync(0xffffffffu, s, 2);
        s += __shfl_down_sync(0xffffffffu, s, 1);
        if (jj == 0) tb[c] = bsh[ii * NC + c] + s;
        __syncthreads();

        // softmax, redundantly per warp
        float t = tb[lane];
        float m = t;
#pragma unroll
        for (int o = 16; o > 0; o >>= 1)
            m = fmaxf(m, __shfl_xor_sync(0xffffffffu, m, o));
        float e = __expf(t - m);
        float se = e;
#pragma unroll
        for (int o = 16; o > 0; o >>= 1)
            se += __shfl_xor_sync(0xffffffffu, se, o);
        float w = e / se;

#pragma unroll
        for (int k = 0; k < 4; k++) {
            int idx2 = tid + 256 * k;
            float wc = __shfl_sync(0xffffffffu, w, 8 * k + warp);
            float2 h = __half22float2(hp[idx2]);
            racc[2 * k] += wc * h.x;
            racc[2 * k + 1] += wc * h.y;
        }
    }

#pragma unroll
    for (int k = 0; k < 4; k++) {
        int idx2 = tid + 256 * k;
        atomicAdd(&Sout[b * (NC * QQ) + idx2 * 2], racc[2 * k]);
        atomicAdd(&Sout[b * (NC * QQ) + idx2 * 2 + 1], racc[2 * k + 1]);
    }
}

// ---------------- squash ----------------
__global__ void squash_kernel(int mode, float* __restrict__ dout) {
    const float* S = (mode == 0) ? g_S0 : (mode == 1) ? g_S1 : g_S2;
    int vec = blockIdx.x;  // b*NC + c
    int lane = threadIdx.x;
    float x0 = S[vec * QQ + lane];
    float x1 = S[vec * QQ + 32 + lane];
    float ss = x0 * x0 + x1 * x1;
#pragma unroll
    for (int o = 16; o > 0; o >>= 1)
        ss += __shfl_xor_sync(0xffffffffu, ss, o);
    float sc = (ss > 0.f) ? (ss / (1.f + ss)) * rsqrtf(ss) : 0.f;
    float o0 = sc * x0, o1 = sc * x1;
    if (mode == 0) {
        g_v0[vec * QQ + lane] = o0;
        g_v0[vec * QQ + 32 + lane] = o1;
    } else if (mode == 1) {
        g_v01[vec * QQ + lane] = g_v0[vec * QQ + lane] + o0;
        g_v01[vec * QQ + 32 + lane] = g_v0[vec * QQ + 32 + lane] + o1;
    } else {
        dout[vec * QQ + lane] = o0;
        dout[vec * QQ + 32 + lane] = o1;
    }
}

// ---------------- launch ----------------
extern "C" void kernel_launch(void* const* d_in, const int* in_sizes, int n_in,
                              void* d_out, int out_size) {
    const float* x = (const float*)d_in[0];     // [32,1152,64]
    const float* W = (const float*)d_in[1];     // [1152,32,64,64]
    const float* bias = (const float*)d_in[2];  // [1,1152,32,1]
    float* out = (float*)d_out;                 // [32,32,64]

    static int smem_set = 0;
    if (!smem_set) {
        cudaFuncSetAttribute(gemm_kernel, cudaFuncAttributeMaxDynamicSharedMemorySize,
                             GEMM_SMEM_BYTES);
        smem_set = 1;
    }

    zero_kernel<<<SV / 256, 256>>>();
    bias_softmax_kernel<<<IC, 32>>>(bias);
    gemm_kernel<<<dim3(NC / 2, IC / ICH), 128, GEMM_SMEM_BYTES>>>(x, W);
    squash_kernel<<<BB * NC, 32>>>(0, out);
    route_kernel<<<dim3(IC / RICH, BB), 256>>>(1, bias);
    squash_kernel<<<BB * NC, 32>>>(1, out);
    route_kernel<<<dim3(IC / RICH, BB), 256>>>(2, bias);
    squash_kernel<<<BB * NC, 32>>>(2, out);
}